// round 10
// baseline (speedup 1.0000x reference)
#include <cuda_runtime.h>
#include <cooperative_groups.h>
#include <cstdint>
#include <math.h>

namespace cg = cooperative_groups;

// ---------------- Problem constants ----------------
#define BB    32
#define SS    512
#define EE    512
#define HH    256
#define H4    1024
#define H2    512
#define MM    (BB*SS)      // 16384
#define NSLOT 128
#define NINT  64

// ---------------- Scratch (device globals; no allocation allowed) ----------------
__device__ float g_pre[(size_t)MM*2048];
__device__ float g_out0[(size_t)MM*H2];     // layer-0 out; later reused as out1^T
__device__ float g_out1[(size_t)MM*H2];
__device__ float g_scores[(size_t)MM*H2];   // scores; later reused as A_tmp
__device__ float g_slotctx[(size_t)MM*H2];
__device__ float g_icl[BB*H2];
__device__ float g_wvsum[H2];
__device__ float g_bvsum[1];

// ---------------- packed f32x2 helpers (LSTM) ----------------
#define FMAX2(d, a, b, c) \
    asm("fma.rn.f32x2 %0, %1, %2, %3;" : "=l"(d) : "l"(a), "l"(b), "l"(c))
#define F4TOX2(v, a, b) \
    asm("mov.b64 %0, {%2, %3};\n\tmov.b64 %1, {%4, %5};" \
        : "=l"(a), "=l"(b) : "f"((v).x), "f"((v).y), "f"((v).z), "f"((v).w))
#define UNPX2(lo, hi, v) \
    asm("mov.b64 {%0, %1}, %2;" : "=f"(lo), "=f"(hi) : "l"(v))

#define CLUSTER_ARRIVE() asm volatile("barrier.cluster.arrive.aligned;" ::: "memory")
#define CLUSTER_WAIT()   asm volatile("barrier.cluster.wait.aligned;"   ::: "memory")

__device__ __forceinline__ float sigm_f(float x) {
    return __fdividef(1.f, 1.f + __expf(-x));
}
__device__ __forceinline__ float tanh_f(float x) {
    return __fdividef(2.f, 1.f + __expf(-2.f * x)) - 1.f;
}

// ---------------- mma.sync helpers (sm_80+ baseline; OK on sm_100 base target) ----------------
__device__ __forceinline__ uint32_t smem_u32(const void* p) {
    uint32_t a;
    asm("{ .reg .u64 t; cvta.to.shared.u64 t, %1; cvt.u32.u64 %0, t; }" : "=r"(a) : "l"(p));
    return a;
}
#define LDSM4(r, addr) \
    asm volatile("ldmatrix.sync.aligned.m8n8.x4.shared.b16 {%0,%1,%2,%3}, [%4];" \
                 : "=r"((r)[0]), "=r"((r)[1]), "=r"((r)[2]), "=r"((r)[3]) : "r"(addr))
#define LDSM2(r, addr) \
    asm volatile("ldmatrix.sync.aligned.m8n8.x2.shared.b16 {%0,%1}, [%2];" \
                 : "=r"((r)[0]), "=r"((r)[1]) : "r"(addr))
#define MMA16816(c, a, b) \
    asm volatile("mma.sync.aligned.m16n8k16.row.col.f32.bf16.bf16.f32 " \
                 "{%0,%1,%2,%3}, {%4,%5,%6,%7}, {%8,%9}, {%0,%1,%2,%3};" \
                 : "+f"((c)[0]), "+f"((c)[1]), "+f"((c)[2]), "+f"((c)[3]) \
                 : "r"((a)[0]), "r"((a)[1]), "r"((a)[2]), "r"((a)[3]), \
                   "r"((b)[0]), "r"((b)[1]))

// bf16 split: hi = truncate-to-bf16(f), lo = rn-bf16(f - hi); packed bf16x2 per u32
__device__ __forceinline__ void split8(float4 x0, float4 x1, uint32_t* hi, uint32_t* lo) {
    float f[8] = {x0.x, x0.y, x0.z, x0.w, x1.x, x1.y, x1.z, x1.w};
#pragma unroll
    for (int p = 0; p < 4; ++p) {
        uint32_t u0 = __float_as_uint(f[2*p])   & 0xFFFF0000u;
        uint32_t u1 = __float_as_uint(f[2*p+1]) & 0xFFFF0000u;
        hi[p] = (u0 >> 16) | u1;
        float r0 = f[2*p]   - __uint_as_float(u0);
        float r1 = f[2*p+1] - __uint_as_float(u1);
        asm("cvt.rn.bf16x2.f32 %0, %1, %2;" : "=r"(lo[p]) : "f"(r1), "f"(r0));
    }
}

__device__ __forceinline__ uint32_t sw128(uint32_t off) {
    return off ^ ((off >> 3) & 0x70);
}

// ---------------- split-bf16 HMMA GEMM: C = A @ B^T + bias ----------------
// A: M x K fp32 (opt. gathered rows), B: N x K fp32. K%64==0, M,N%128==0.
// 128x128 tile/CTA, 8 warps (2m x 4n), warp tile 64x32, fp32 accum,
// 3 products per k-chunk: AhBh + AhBl + AlBh. ONE sync per k-iter (proof in R9 notes).
#define TCG_TILEB     16384                    // one bf16 tile 128x64
#define TCG_OFF_AH    0
#define TCG_OFF_AL    16384
#define TCG_OFF_BH    32768
#define TCG_OFF_BL    49152
#define TCG_STAGE     65536
#define TCG_SMEM      (2*TCG_STAGE)            // 131072

template<bool GATHER>
__global__ void __launch_bounds__(256) tc_gemm(
    const float* __restrict__ A, const float* __restrict__ Bm,
    const float* __restrict__ bias, float* __restrict__ C,
    int M, int N, int K,
    long sA, long sB, long sC,
    const int* __restrict__ gidx, const float* __restrict__ gtab)
{
    extern __shared__ char smem[];
    const uint32_t sbase = smem_u32(smem);
    const int tid = threadIdx.x;
    const int wid = tid >> 5, lane = tid & 31;
    const int wm = wid >> 2, wn = wid & 3;      // warp grid 2 x 4
    const int nbase = blockIdx.x * 128;
    const int mbase = blockIdx.y * 128;

    const float* Ab = GATHER ? gtab : (A + blockIdx.z * sA);
    const float* Bb = Bm + blockIdx.z * sB;
    float*       Cb = C  + blockIdx.z * sC;

    // per-thread load slots: 4 x (row = g>>3, kg = g&7)
    int rowv[4]; long aoffv[4];
#pragma unroll
    for (int i = 0; i < 4; ++i) {
        const int g = tid + i * 256;
        rowv[i] = g >> 3;
        aoffv[i] = GATHER ? (long)gidx[mbase + rowv[i]] * K
                          : (long)(mbase + rowv[i]) * K;
    }
    const int kgq = (tid & 7) * 8;              // k offset (floats) within chunk

    float4 rA[4][2], rB[4][2];
    auto ldg_chunk = [&](int kc) {
#pragma unroll
        for (int i = 0; i < 4; ++i) {
            const float4* ap = (const float4*)(Ab + aoffv[i] + kc + kgq);
            rA[i][0] = ap[0]; rA[i][1] = ap[1];
            const float4* bp = (const float4*)(Bb + (long)(nbase + rowv[i]) * K + kc + kgq);
            rB[i][0] = bp[0]; rB[i][1] = bp[1];
        }
    };
    auto sts_chunk = [&](int stg) {
        char* db = smem + stg * TCG_STAGE;
#pragma unroll
        for (int i = 0; i < 4; ++i) {
            const uint32_t off = sw128((uint32_t)(rowv[i] * 128 + (tid & 7) * 16));
            uint32_t hi[4], lo[4];
            split8(rA[i][0], rA[i][1], hi, lo);
            *(uint4*)(db + TCG_OFF_AH + off) = make_uint4(hi[0], hi[1], hi[2], hi[3]);
            *(uint4*)(db + TCG_OFF_AL + off) = make_uint4(lo[0], lo[1], lo[2], lo[3]);
            split8(rB[i][0], rB[i][1], hi, lo);
            *(uint4*)(db + TCG_OFF_BH + off) = make_uint4(hi[0], hi[1], hi[2], hi[3]);
            *(uint4*)(db + TCG_OFF_BL + off) = make_uint4(lo[0], lo[1], lo[2], lo[3]);
        }
    };

    float acc[4][4][4];
#pragma unroll
    for (int mt = 0; mt < 4; ++mt)
#pragma unroll
        for (int nt = 0; nt < 4; ++nt)
#pragma unroll
            for (int q = 0; q < 4; ++q) acc[mt][nt][q] = 0.f;

    // ldmatrix address offsets (within a tile)
    const uint32_t aoffm = sw128((uint32_t)((wm * 64 + (lane & 15)) * 128 + (lane >> 4) * 16));
    const uint32_t boffm = sw128((uint32_t)((wn * 32 + (lane & 7)) * 128 + ((lane >> 3) & 1) * 16));

    ldg_chunk(0);
    const int NC = K >> 6;
    for (int c = 0; c < NC; ++c) {
        const int s = c & 1;
        sts_chunk(s);
        __syncthreads();      // single sync per iter: safe (reads of stage s complete
                              // before any warp's sts of stage s two iterations later)
        if (c + 1 < NC) ldg_chunk((c + 1) << 6);

        const uint32_t bAh = sbase + s * TCG_STAGE + TCG_OFF_AH;
        const uint32_t bAl = sbase + s * TCG_STAGE + TCG_OFF_AL;
        const uint32_t bBh = sbase + s * TCG_STAGE + TCG_OFF_BH;
        const uint32_t bBl = sbase + s * TCG_STAGE + TCG_OFF_BL;
#pragma unroll
        for (int kb = 0; kb < 4; ++kb) {
            // XOR k-step valid: sw128 mixes bits [9:7]->[6:4]; bit5 untouched.
            const uint32_t kx = kb * 32;
            uint32_t ah[4][4], al[4][4];
#pragma unroll
            for (int mt = 0; mt < 4; ++mt) {
                const uint32_t o = (aoffm + mt * 16 * 128) ^ kx;
                LDSM4(ah[mt], bAh + o);
                LDSM4(al[mt], bAl + o);
            }
            uint32_t bh[4][2], bl[4][2];
#pragma unroll
            for (int nt = 0; nt < 4; ++nt) {
                const uint32_t o = (boffm + nt * 8 * 128) ^ kx;
                LDSM2(bh[nt], bBh + o);
                LDSM2(bl[nt], bBl + o);
            }
#pragma unroll
            for (int mt = 0; mt < 4; ++mt)
#pragma unroll
                for (int nt = 0; nt < 4; ++nt) {
                    MMA16816(acc[mt][nt], ah[mt], bh[nt]);
                    MMA16816(acc[mt][nt], ah[mt], bl[nt]);
                    MMA16816(acc[mt][nt], al[mt], bh[nt]);
                }
        }
    }

    // epilogue
#pragma unroll
    for (int mt = 0; mt < 4; ++mt) {
        const int row = mbase + wm * 64 + mt * 16 + (lane >> 2);
#pragma unroll
        for (int nt = 0; nt < 4; ++nt) {
            const int col = nbase + wn * 32 + nt * 8 + (lane & 3) * 2;
            const float b0 = bias ? bias[col] : 0.f;
            const float b1 = bias ? bias[col + 1] : 0.f;
            float2 v0 = make_float2(acc[mt][nt][0] + b0, acc[mt][nt][1] + b1);
            float2 v1 = make_float2(acc[mt][nt][2] + b0, acc[mt][nt][3] + b1);
            *(float2*)(Cb + (long)row * N + col)       = v0;
            *(float2*)(Cb + (long)(row + 8) * N + col) = v1;
        }
    }
}

// ---------------- batched 512x512 transpose: outT[b][d][s] = in[b][s][d] ----------------
__global__ void __launch_bounds__(256) transpose512(
    const float* __restrict__ in, float* __restrict__ outT)
{
    __shared__ float t[32][33];
    const int b = blockIdx.z;
    const int s0 = blockIdx.x * 32, d0 = blockIdx.y * 32;
    const float* ib = in  + (long)b * 512 * 512;
    float*       ob = outT + (long)b * 512 * 512;
    const int x = threadIdx.x & 31, y = threadIdx.x >> 5;
#pragma unroll
    for (int i = y; i < 32; i += 8)
        t[i][x] = ib[(long)(s0 + i) * 512 + d0 + x];
    __syncthreads();
#pragma unroll
    for (int i = y; i < 32; i += 8)
        ob[(long)(d0 + i) * 512 + s0 + x] = t[x][i];
}

// ---------------- BiLSTM recurrence (v3c: STG/LDG latency under cluster barrier) ----------------
#define HB_PITCH 5
#define HB_BATCH (16*HB_PITCH)
#define HB_TOT   (4*HB_BATCH)
#define GPF      132

__global__ void __cluster_dims__(8, 1, 1) __launch_bounds__(512, 1)
lstm_kernel(const float* __restrict__ pre, const float* __restrict__ Whh,
            const float* __restrict__ bhh, float* __restrict__ out)
{
    __shared__ float4 sHbuf[2][HB_TOT];
    __shared__ float  sGp[16*GPF];
    __shared__ float  sAct[4*GPF];
    __shared__ float  sStage[128];
    __shared__ float  sBhh[128];
    __shared__ float  sC[128];

    cg::cluster_group cluster = cg::this_cluster();
    const int rank = cluster.block_rank();
    const int cid  = blockIdx.x >> 3;
    const int dir  = cid & 1;
    const int b0   = (cid >> 1) * 4;
    const int tid  = threadIdx.x;

    const int rg = tid >> 4;
    const int ks = tid & 15;
    const int r0 = rg * 4;
    const int pb = tid >> 7;
    const int pr = tid & 127;
    const int grow_pr = (pr >> 5) * 256 + rank * 32 + (pr & 31);

    unsigned long long wr2[4][8];
    {
        const int type0 = r0 >> 5;
#pragma unroll
        for (int i = 0; i < 4; ++i) {
            const int gr = type0 * 256 + rank * 32 + ((r0 + i) & 31);
            const float4* W4 = (const float4*)(Whh + ((long)(dir * 1024 + gr)) * 256 + ks * 16);
#pragma unroll
            for (int q = 0; q < 4; ++q) {
                float4 w = W4[q];
                F4TOX2(w, wr2[i][q * 2], wr2[i][q * 2 + 1]);
            }
        }
    }
    if (tid < 128) {
        sBhh[tid] = bhh[dir * 1024 + (tid >> 5) * 256 + rank * 32 + (tid & 31)];
        sC[tid] = 0.f;
    }
    {
        float4 z = make_float4(0.f, 0.f, 0.f, 0.f);
        for (int i = tid; i < 2 * HB_TOT; i += 512) ((float4*)sHbuf)[i] = z;
    }
    __syncthreads();
    CLUSTER_ARRIVE(); CLUSTER_WAIT();

    const long pstride = dir ? -2048L : 2048L;
    const float* pp = pre + ((long)((b0 + pb) * 512 + (dir ? 511 : 0))) * 2048
                          + dir * 1024 + grow_pr;
    float* op = out;
    long ostride = 0;
    if (tid < 128) {
        const int cb = tid >> 5, cj = tid & 31;
        op = out + ((long)((b0 + cb) * 512 + (dir ? 511 : 0))) * 512
                 + dir * 256 + rank * 32 + cj;
        ostride = dir ? -512L : 512L;
    }
    float4 *rbuf0 = 0, *rbuf1 = 0;
    int srcidx = 0, dstoff = 0;
    if (tid < 256) {
        const int peer = tid >> 5;
        const int idx = tid & 31, b = idx >> 3, q = idx & 7;
        srcidx = idx;
        dstoff = b * HB_BATCH + (rank * 2 + (q >> 2)) * HB_PITCH + (q & 3);
        rbuf0 = (float4*)cluster.map_shared_rank(&sHbuf[0][0], peer);
        rbuf1 = (float4*)cluster.map_shared_rank(&sHbuf[1][0], peer);
    }

    int par = 0;
    float preg = __ldg(pp); pp += pstride;   // t=0 prefetch

    for (int t = 0; t < 512; ++t) {
        // ---- phase A: gate partial dots (h from buf par) ----
        const float4* hb = &sHbuf[par][0];
        float v[4][4];
#pragma unroll
        for (int b = 0; b < 4; ++b) {
            const float4* hp = hb + b * HB_BATCH + ks * HB_PITCH;
            float4 v0 = hp[0], v1 = hp[1], v2 = hp[2], v3 = hp[3];
            unsigned long long h2[8];
            F4TOX2(v0, h2[0], h2[1]);
            F4TOX2(v1, h2[2], h2[3]);
            F4TOX2(v2, h2[4], h2[5]);
            F4TOX2(v3, h2[6], h2[7]);
#pragma unroll
            for (int i = 0; i < 4; ++i) {
                unsigned long long a = 0ULL;
#pragma unroll
                for (int kp = 0; kp < 8; ++kp)
                    FMAX2(a, wr2[i][kp], h2[kp], a);
                float lo, hi;
                UNPX2(lo, hi, a);
                float s = lo + hi;
                s += __shfl_xor_sync(0xffffffffu, s, 1);
                s += __shfl_xor_sync(0xffffffffu, s, 2);
                v[i][b] = s;
            }
        }
        if ((ks & 3) == 0) {
            const int q = ks >> 2;
#pragma unroll
            for (int b = 0; b < 4; ++b)
                ((float4*)sGp)[(q * 4 + b) * (GPF / 4) + rg] =
                    make_float4(v[0][b], v[1][b], v[2][b], v[3][b]);
        }
        __syncthreads();

        // ---- phase B: combine partials + activation (gate-parallel) ----
        {
            float s = sGp[(0 * 4 + pb) * GPF + pr] + sGp[(1 * 4 + pb) * GPF + pr]
                    + sGp[(2 * 4 + pb) * GPF + pr] + sGp[(3 * 4 + pb) * GPF + pr];
            s += preg + sBhh[pr];
            const int type = pr >> 5;
            sAct[pb * GPF + pr] = (type == 2) ? tanh_f(s) : sigm_f(s);
        }
        __syncthreads();

        // ---- phase C: cell update (out store deferred past arrive) ----
        float hval = 0.f;
        if (tid < 128) {
            const int cb = tid >> 5, cj = tid & 31;
            const float gi = sAct[cb * GPF + cj];
            const float gf = sAct[cb * GPF + 32 + cj];
            const float gg = sAct[cb * GPF + 64 + cj];
            const float go = sAct[cb * GPF + 96 + cj];
            float c = gf * sC[tid] + gi * gg;
            sC[tid] = c;
            hval = go * tanh_f(c);
            sStage[cb * 32 + cj] = hval;
        }
        __syncthreads();

        // ---- push h to all peers' next buffer, then hide STG/LDG under barrier ----
        if (tid < 256) {
            const float4 vsh = ((const float4*)sStage)[srcidx];
            (par ? rbuf0 : rbuf1)[dstoff] = vsh;
        }
        CLUSTER_ARRIVE();
        if (tid < 128) { *op = hval; op += ostride; }
        if (t + 1 < 512) { preg = __ldg(pp); pp += pstride; }
        CLUSTER_WAIT();
        par ^= 1;
    }
}

// ---------------- softmax over 512-wide rows, in place ----------------
__global__ void __launch_bounds__(256) softmax512(float* __restrict__ Sc)
{
    __shared__ float red[256];
    const long base = (long)blockIdx.x * 512;
    const int tid = threadIdx.x;
    float v0 = Sc[base + tid], v1 = Sc[base + tid + 256];
    red[tid] = fmaxf(v0, v1);
    __syncthreads();
    for (int s = 128; s > 0; s >>= 1) {
        if (tid < s) red[tid] = fmaxf(red[tid], red[tid + s]);
        __syncthreads();
    }
    float m = red[0];
    __syncthreads();
    float e0 = expf(v0 - m), e1 = expf(v1 - m);
    red[tid] = e0 + e1;
    __syncthreads();
    for (int s = 128; s > 0; s >>= 1) {
        if (tid < s) red[tid] += red[tid + s];
        __syncthreads();
    }
    float inv = 1.f / red[0];
    Sc[base + tid]       = e0 * inv;
    Sc[base + tid + 256] = e1 * inv;
}

// ---------------- Wv column sum (parallel: 32 blocks) ----------------
__global__ void __launch_bounds__(512) wvsum_kernel(
    const float* __restrict__ Wv, const float* __restrict__ bv)
{
    __shared__ float part[512];
    const int tid = threadIdx.x;
    const int kk = tid & 15;               // 16 k per block
    const int jr = tid >> 4;               // 32 j-ranges
    const int k  = blockIdx.x * 16 + kk;
    float s = 0.f;
#pragma unroll 4
    for (int j = jr * 16; j < jr * 16 + 16; ++j)
        s += Wv[(long)j * 512 + k];
    part[tid] = s;
    __syncthreads();
    if (tid < 16) {
        float t = 0.f;
#pragma unroll
        for (int m = 0; m < 32; ++m) t += part[m * 16 + tid];
        g_wvsum[blockIdx.x * 16 + tid] = t;
    }
    if (blockIdx.x == 0 && tid == 16) {
        float t = 0.f;
        for (int j = 0; j < 512; ++j) t += bv[j];
        g_bvsum[0] = t;
    }
}

// ---------------- intent head (per batch) + intent broadcast ----------------
__global__ void __launch_bounds__(256) intent_kernel(
    const float* __restrict__ out1, const float* __restrict__ Wg, const float* __restrict__ bg,
    const float* __restrict__ Wint, const float* __restrict__ bint,
    float* __restrict__ icl_out, float* __restrict__ int_out)
{
    __shared__ float sq[512], sw[512], sctx[512], siv[64], red[256];
    const int b = blockIdx.x, tid = threadIdx.x;
    const int lane = tid & 31, w = tid >> 5;
    const float* ob = out1 + (long)b * 512 * 512;

    sq[tid] = ob[(long)511 * 512 + tid];
    sq[tid + 256] = ob[(long)511 * 512 + tid + 256];
    __syncthreads();

    for (int s = w; s < 512; s += 8) {
        float sum = 0.f;
        for (int k = lane; k < 512; k += 32) sum += sq[k] * ob[(long)s * 512 + k];
#pragma unroll
        for (int off = 16; off; off >>= 1) sum += __shfl_xor_sync(0xffffffffu, sum, off);
        if (lane == 0) sw[s] = sum;
    }
    __syncthreads();

    float v0 = sw[tid], v1 = sw[tid + 256];
    red[tid] = fmaxf(v0, v1);
    __syncthreads();
    for (int s = 128; s > 0; s >>= 1) { if (tid < s) red[tid] = fmaxf(red[tid], red[tid + s]); __syncthreads(); }
    float m = red[0];
    __syncthreads();
    float e0 = expf(v0 - m), e1 = expf(v1 - m);
    red[tid] = e0 + e1;
    __syncthreads();
    for (int s = 128; s > 0; s >>= 1) { if (tid < s) red[tid] += red[tid + s]; __syncthreads(); }
    float inv = 1.f / red[0];
    sw[tid] = e0 * inv; sw[tid + 256] = e1 * inv;
    __syncthreads();

    float c0 = 0.f, c1 = 0.f;
    for (int s = 0; s < 512; ++s) {
        float wv = sw[s];
        c0 += wv * ob[(long)s * 512 + tid];
        c1 += wv * ob[(long)s * 512 + tid + 256];
    }
    sctx[tid] = c0; sctx[tid + 256] = c1;
    __syncthreads();

    for (int j = w; j < 512; j += 8) {
        float sum = 0.f;
        for (int k = lane; k < 512; k += 32) sum += Wg[(long)j * 512 + k] * sctx[k];
#pragma unroll
        for (int off = 16; off; off >>= 1) sum += __shfl_xor_sync(0xffffffffu, sum, off);
        if (lane == 0) icl_out[b * 512 + j] = sum + bg[j];
    }
    for (int j = w; j < 64; j += 8) {
        float sum = 0.f;
        for (int k = lane; k < 512; k += 32) sum += Wint[(long)j * 512 + k] * (sctx[k] + sq[k]);
#pragma unroll
        for (int off = 16; off; off >>= 1) sum += __shfl_xor_sync(0xffffffffu, sum, off);
        if (lane == 0) siv[j] = sum + bint[j];
    }
    __syncthreads();

    for (int i = tid; i < 512 * 64; i += 256) {
        int t = i >> 6, j = i & 63;
        int_out[((long)b * 512 + t) * 64 + j] = siv[j];
    }
}

// ---------------- gate + build A_tmp = gate*slot_ctx + out1 ----------------
__global__ void __launch_bounds__(256) gate_kernel(
    const float* __restrict__ ctx, const float* __restrict__ icl,
    const float* __restrict__ out1, float* __restrict__ Atmp)
{
    const int w = threadIdx.x >> 5, lane = threadIdx.x & 31;
    const long row = (long)blockIdx.x * 8 + w;
    const int b = (int)(row >> 9);
    const float* cr = ctx + row * 512;
    const float* ir = icl + (long)b * 512;
    float sum = 0.f;
    for (int k = lane; k < 512; k += 32)
        sum += tanhf(cr[k] + ir[k]) * g_wvsum[k];
#pragma unroll
    for (int off = 16; off; off >>= 1) sum += __shfl_xor_sync(0xffffffffu, sum, off);
    float gate = sum + g_bvsum[0];
    const float* orow = out1 + row * 512;
    float* arow = Atmp + row * 512;
    for (int k = lane; k < 512; k += 32)
        arow[k] = gate * cr[k] + orow[k];
}

// ---------------- host launcher ----------------
extern "C" void kernel_launch(void* const* d_in, const int* in_sizes, int n_in,
                              void* d_out, int out_size)
{
    const int*   src   = (const int*)  d_in[0];
    const float* emb   = (const float*)d_in[2];
    const float* Wih   = (const float*)d_in[3];
    const float* Whh   = (const float*)d_in[4];
    const float* bih   = (const float*)d_in[5];
    const float* bhh   = (const float*)d_in[6];
    const float* Wg    = (const float*)d_in[7];
    const float* bg    = (const float*)d_in[8];
    const float* Wv    = (const float*)d_in[9];
    const float* bv    = (const float*)d_in[10];
    const float* Wslot = (const float*)d_in[11];
    const float* bslot = (const float*)d_in[12];
    const float* Wint  = (const float*)d_in[13];
    const float* bint  = (const float*)d_in[14];

    float* out       = (float*)d_out;
    float* slot_out  = out;
    float* int_out   = out + (size_t)MM * NSLOT;

    float *p_pre = 0, *p_out0 = 0, *p_out1 = 0, *p_scores = 0, *p_slotctx = 0, *p_icl = 0;
    (void)cudaGetSymbolAddress((void**)&p_pre,     g_pre);
    (void)cudaGetSymbolAddress((void**)&p_out0,    g_out0);
    (void)cudaGetSymbolAddress((void**)&p_out1,    g_out1);
    (void)cudaGetSymbolAddress((void**)&p_scores,  g_scores);
    (void)cudaGetSymbolAddress((void**)&p_slotctx, g_slotctx);
    (void)cudaGetSymbolAddress((void**)&p_icl,     g_icl);

    (void)cudaFuncSetAttribute((const void*)tc_gemm<true>,
                               cudaFuncAttributeMaxDynamicSharedMemorySize, TCG_SMEM);
    (void)cudaFuncSetAttribute((const void*)tc_gemm<false>,
                               cudaFuncAttributeMaxDynamicSharedMemorySize, TCG_SMEM);

    // 0: wv colsum (parallel)
    wvsum_kernel<<<32, 512>>>(Wv, bv);

    // 1: layer-0 input projection (embedding gather fused)
    {
        dim3 grid(2048 / 128, MM / 128, 1);
        tc_gemm<true><<<grid, 256, TCG_SMEM>>>(nullptr, Wih, bih, p_pre,
                                               MM, 2048, EE, 0, 0, 0, src, emb);
    }
    // 2: layer-0 recurrence
    lstm_kernel<<<128, 512>>>(p_pre, Whh, bhh, p_out0);

    // 3: layer-1 input projection
    {
        dim3 grid(2048 / 128, MM / 128, 1);
        tc_gemm<false><<<grid, 256, TCG_SMEM>>>(p_out0, Wih + (size_t)2048 * 512,
                                                bih + 2048, p_pre,
                                                MM, 2048, H2, 0, 0, 0, nullptr, nullptr);
    }
    // 4: layer-1 recurrence
    lstm_kernel<<<128, 512>>>(p_pre, Whh + (size_t)2 * H4 * HH,
                              bhh + 2048, p_out1);

    // 5: attention scores: per-batch out @ out^T
    {
        dim3 grid(512 / 128, 512 / 128, BB);
        tc_gemm<false><<<grid, 256, TCG_SMEM>>>(p_out1, p_out1, nullptr, p_scores,
                                                512, 512, 512,
                                                (long)512 * 512, (long)512 * 512, (long)512 * 512,
                                                nullptr, nullptr);
    }
    softmax512<<<MM, 256>>>(p_scores);

    // transpose out1 -> g_out0 (per batch): outT[d][s]
    {
        dim3 grid(16, 16, BB);
        transpose512<<<grid, 256>>>(p_out1, p_out0);
    }
    // slot_ctx = w @ out  (B = outT, K-major)
    {
        dim3 grid(512 / 128, 512 / 128, BB);
        tc_gemm<false><<<grid, 256, TCG_SMEM>>>(p_scores, p_out0, nullptr, p_slotctx,
                                                512, 512, 512,
                                                (long)512 * 512, (long)512 * 512, (long)512 * 512,
                                                nullptr, nullptr);
    }
    intent_kernel<<<BB, 256>>>(p_out1, Wg, bg, Wint, bint, p_icl, int_out);

    gate_kernel<<<MM / 8, 256>>>(p_slotctx, p_icl, p_out1, p_scores);

    // slot_outputs = A_tmp @ Wslot^T + bslot
    {
        dim3 grid(NSLOT / 128, MM / 128, 1);
        tc_gemm<false><<<grid, 256, TCG_SMEM>>>(p_scores, Wslot, bslot, slot_out,
                                                MM, NSLOT, H2, 0, 0, 0, nullptr, nullptr);
    }
}